// round 7
// baseline (speedup 1.0000x reference)
#include <cuda_runtime.h>
#include <cuda_bf16.h>

// Shapes (fixed per reference)
#define S_DIM   64
#define C_DIM   384
#define HW      3136          // 56*56
#define HW4     784           // HW/4 (float4 quads per channel plane)
#define CHW     (C_DIM * HW)  // 1204224 floats per frame
#define S_TOP   16
#define CNUM    48            // C_DIM / 8

#define SEG     8             // frames per conv segment
#define NSEG    (S_DIM / SEG) // 8
#define NQUADS  (C_DIM * HW4) // 301056 (c, quad) tasks
#define CONV_T  256           // conv block size
#define BLK_PER_SEG (NQUADS / CONV_T)  // 1176, exact

// Scratch (no device allocation allowed)
__device__ float g_xg[S_DIM * C_DIM];     // per-frame, per-channel means
__device__ float g_convk[C_DIM * 3];      // per-channel temporal kernel (softmaxed)

// ---------------------------------------------------------------------------
// Kernel 1: global average pool. One block per (s,c) plane of 3136 floats.
// Blocks iterate channels DESCENDING (s inner) with evict-NORMAL reads, so
// the L2 residue when pool finishes is the LOW channels — exactly what the
// conv kernel (ascending c) reads first. Free ~126 MB hand-off.
// ---------------------------------------------------------------------------
__global__ void pool_kernel(const float* __restrict__ x) {
    int bx = blockIdx.x;
    int s  = bx % S_DIM;                    // fast: frames within a channel
    int cc = (C_DIM - 1) - (bx / S_DIM);    // slow: channels, high -> low
    int plane = s * C_DIM + cc;             // storage index in x / g_xg
    const float4* p = reinterpret_cast<const float4*>(x + (size_t)plane * HW);
    float sum = 0.f;
    for (int i = threadIdx.x; i < HW4; i += blockDim.x) {
        float4 v = p[i];                    // default policy: stays in L2
        sum += (v.x + v.y) + (v.z + v.w);
    }
    // warp reduce
    #pragma unroll
    for (int off = 16; off > 0; off >>= 1)
        sum += __shfl_down_sync(0xFFFFFFFFu, sum, off);
    __shared__ float warp_sums[4];          // 128 threads = 4 warps
    int lane = threadIdx.x & 31, wid = threadIdx.x >> 5;
    if (lane == 0) warp_sums[wid] = sum;
    __syncthreads();
    if (threadIdx.x == 0) {
        float t = warp_sums[0] + warp_sums[1] + warp_sums[2] + warp_sums[3];
        g_xg[plane] = t * (1.0f / (float)HW);
    }
}

// ---------------------------------------------------------------------------
// Kernel 2: scores -> stable top-16 (temporal order) -> per-channel MLP ->
// softmax temporal kernel. Single block, 384 threads (12 warps).
// ---------------------------------------------------------------------------
__global__ void mlp_kernel(const float* __restrict__ w_lin,
                           const float* __restrict__ w1,
                           const float* __restrict__ bn_gamma,
                           const float* __restrict__ bn_beta,
                           const float* __restrict__ bn_mean,
                           const float* __restrict__ bn_var,
                           const float* __restrict__ w2) {
    __shared__ float sc[S_DIM];
    __shared__ int   flag[S_DIM];
    __shared__ int   idx[S_TOP];
    int t    = threadIdx.x;
    int lane = t & 31;
    int wid  = t >> 5;                      // 0..11

    // --- scores: xgs[s] = dot(xg[s,:], w_lin); one warp per frame ---
    for (int s = wid; s < S_DIM; s += 12) {
        const float* row = g_xg + s * C_DIM;
        float acc = 0.f;
        #pragma unroll
        for (int j = 0; j < C_DIM / 32; j++) {          // 12 elements per lane
            int c = lane + j * 32;
            acc = fmaf(row[c], w_lin[c], acc);
        }
        #pragma unroll
        for (int off = 16; off > 0; off >>= 1)
            acc += __shfl_down_sync(0xFFFFFFFFu, acc, off);
        if (lane == 0) sc[s] = acc;
    }
    __syncthreads();

    // --- stable rank: rank(i) = #{j : sc[j] > sc[i] or (== and j < i)} ---
    if (t < S_DIM) {
        float si = sc[t];
        int rank = 0;
        #pragma unroll 8
        for (int j = 0; j < S_DIM; j++) {
            float sj = sc[j];
            rank += (sj > si || (sj == si && j < t)) ? 1 : 0;
        }
        flag[t] = (rank < S_TOP) ? 1 : 0;
    }
    __syncthreads();
    if (t == 0) {                            // trivial 64-iter compaction
        int n = 0;
        for (int i = 0; i < S_DIM; i++)
            if (flag[i] && n < S_TOP) idx[n++] = i;
    }
    __syncthreads();

    // --- per-channel kernel-generating MLP ---
    if (t < C_DIM) {
        float sls[S_TOP];
        #pragma unroll
        for (int j = 0; j < S_TOP; j++) sls[j] = g_xg[idx[j] * C_DIM + t];

        float l0 = 0.f, l1 = 0.f, l2 = 0.f;
        #pragma unroll 4
        for (int k = 0; k < 2 * S_TOP; k++) {
            float acc = 0.f;
            const float* w1row = w1 + k * S_TOP;
            #pragma unroll
            for (int j = 0; j < S_TOP; j++) acc = fmaf(sls[j], w1row[j], acc);
            // BN (eval mode) + ReLU
            float scale = bn_gamma[k] * rsqrtf(bn_var[k] + 1e-5f);
            acc = fmaf(acc - bn_mean[k], scale, bn_beta[k]);
            acc = fmaxf(acc, 0.f);
            l0 = fmaf(acc, w2[0 * 2 * S_TOP + k], l0);
            l1 = fmaf(acc, w2[1 * 2 * S_TOP + k], l1);
            l2 = fmaf(acc, w2[2 * 2 * S_TOP + k], l2);
        }
        float mx = fmaxf(l0, fmaxf(l1, l2));
        float e0 = __expf(l0 - mx), e1 = __expf(l1 - mx), e2 = __expf(l2 - mx);
        float inv = 1.0f / (e0 + e1 + e2);
        g_convk[t * 3 + 0] = e0 * inv;
        g_convk[t * 3 + 1] = e1 * inv;
        g_convk[t * 3 + 2] = e2 * inv;
    }
}

// ---------------------------------------------------------------------------
// Kernel 3: channel shift + depthwise temporal conv (k=3, zero pad).
// Batch-load SEG+2 float4s, then FMA + STG burst. seg is the FAST block dim
// (same-wave halo reuse). Reads are __ldcs (evict-first): they hit the pool's
// L2 residue without evicting the not-yet-consumed part of it; writes __stcs.
// ---------------------------------------------------------------------------
__global__ void __launch_bounds__(CONV_T)
conv_kernel(const float* __restrict__ x, float* __restrict__ out) {
    int b     = blockIdx.x;
    int seg   = b & (NSEG - 1);              // fast dim: waves mix all segments
    int chunk = b >> 3;                      // 0 .. BLK_PER_SEG-1
    int task  = chunk * CONV_T + threadIdx.x;   // < NQUADS (exact multiple)
    int c = task / HW4;
    int q = task - c * HW4;
    size_t base = (size_t)c * HW + (size_t)q * 4;   // float index, 16B aligned
    int t0 = seg * SEG;

    // channel shift: c<48 -> read x[s+1]; 48<=c<96 -> x[s-1]; else x[s]
    int d = (c < CNUM) ? 1 : ((c < 2 * CNUM) ? -1 : 0);

    float k0 = g_convk[c * 3 + 0];
    float k1 = g_convk[c * 3 + 1];
    float k2 = g_convk[c * 3 + 2];

    const float4 zero4 = make_float4(0.f, 0.f, 0.f, 0.f);

    // Phase 1: batch load t0-1 .. t0+SEG (SEG+2 independent LDG.128)
    float4 v[SEG + 2];
    #pragma unroll
    for (int i = 0; i < SEG + 2; i++) {
        int t  = t0 - 1 + i;
        int ts = t + d;
        v[i] = ((unsigned)t < (unsigned)S_DIM && (unsigned)ts < (unsigned)S_DIM)
             ? __ldcs(reinterpret_cast<const float4*>(x + (size_t)ts * CHW + base))
             : zero4;
    }

    // Phase 2: FMA + store burst
    #pragma unroll
    for (int i = 0; i < SEG; i++) {
        float4 a = v[i], bb = v[i + 1], cc = v[i + 2];
        float4 o;
        o.x = fmaf(k0, a.x, fmaf(k1, bb.x, k2 * cc.x));
        o.y = fmaf(k0, a.y, fmaf(k1, bb.y, k2 * cc.y));
        o.z = fmaf(k0, a.z, fmaf(k1, bb.z, k2 * cc.z));
        o.w = fmaf(k0, a.w, fmaf(k1, bb.w, k2 * cc.w));
        __stcs(reinterpret_cast<float4*>(out + (size_t)(t0 + i) * CHW + base), o);
    }
}

// ---------------------------------------------------------------------------
extern "C" void kernel_launch(void* const* d_in, const int* in_sizes, int n_in,
                              void* d_out, int out_size) {
    const float* x        = (const float*)d_in[0];
    const float* w_lin    = (const float*)d_in[1];
    const float* w1       = (const float*)d_in[2];
    const float* bn_gamma = (const float*)d_in[3];
    const float* bn_beta  = (const float*)d_in[4];
    const float* bn_mean  = (const float*)d_in[5];
    const float* bn_var   = (const float*)d_in[6];
    const float* w2       = (const float*)d_in[7];
    float* out            = (float*)d_out;

    pool_kernel<<<S_DIM * C_DIM, 128>>>(x);
    mlp_kernel<<<1, C_DIM>>>(w_lin, w1, bn_gamma, bn_beta, bn_mean, bn_var, w2);
    conv_kernel<<<NSEG * BLK_PER_SEG, CONV_T>>>(x, out);
}

// round 12
// speedup vs baseline: 1.1083x; 1.1083x over previous
#include <cuda_runtime.h>
#include <cuda_bf16.h>

// Shapes (fixed per reference)
#define S_DIM   64
#define C_DIM   384
#define HW      3136          // 56*56
#define HW4     784           // HW/4 (float4 quads per channel plane)
#define CHW     (C_DIM * HW)  // 1204224 floats per frame
#define S_TOP   16
#define CNUM    48            // C_DIM / 8

#define SEG     8             // frames per conv segment
#define NSEG    (S_DIM / SEG) // 8
#define NQUADS  (C_DIM * HW4) // 301056 (c, quad) tasks
#define CONV_T  256           // conv block size
#define BLK_PER_SEG (NQUADS / CONV_T)  // 1176, exact

// Scratch (no device allocation allowed)
__device__ float g_xg[S_DIM * C_DIM];     // per-frame, per-channel means
__device__ float g_convk[C_DIM * 3];      // per-channel temporal kernel (softmaxed)
__device__ int   g_idx[S_TOP];            // sorted top-16 frame indices

// ---------------------------------------------------------------------------
// Kernel 1: global average pool. One block per (s,c) plane of 3136 floats.
// (R5 config: ascending order, streaming reads.)
// ---------------------------------------------------------------------------
__global__ void pool_kernel(const float* __restrict__ x) {
    int plane = blockIdx.x;                 // = s*C_DIM + c (x is (s,c,h,w) contiguous)
    const float4* p = reinterpret_cast<const float4*>(x + (size_t)plane * HW);
    float sum = 0.f;
    for (int i = threadIdx.x; i < HW4; i += blockDim.x) {
        float4 v = __ldcs(p + i);           // streaming read: evict-first
        sum += (v.x + v.y) + (v.z + v.w);
    }
    // warp reduce
    #pragma unroll
    for (int off = 16; off > 0; off >>= 1)
        sum += __shfl_down_sync(0xFFFFFFFFu, sum, off);
    __shared__ float warp_sums[4];          // 128 threads = 4 warps
    int lane = threadIdx.x & 31, wid = threadIdx.x >> 5;
    if (lane == 0) warp_sums[wid] = sum;
    __syncthreads();
    if (threadIdx.x == 0) {
        float t = warp_sums[0] + warp_sums[1] + warp_sums[2] + warp_sums[3];
        g_xg[plane] = t * (1.0f / (float)HW);
    }
}

// ---------------------------------------------------------------------------
// Kernel 2a: scores + stable top-16 (temporal order) -> g_idx.
// Single block, 512 threads (16 warps): warp-per-frame scores, then
// thread-per-frame stable rank, then trivial compaction.
// ---------------------------------------------------------------------------
__global__ void mlp_topk_kernel(const float* __restrict__ w_lin) {
    __shared__ float sc[S_DIM];
    __shared__ int   flag[S_DIM];
    int t    = threadIdx.x;
    int lane = t & 31;
    int wid  = t >> 5;                      // 0..15

    // --- scores: xgs[s] = dot(xg[s,:], w_lin); one warp per frame ---
    #pragma unroll
    for (int r = 0; r < S_DIM / 16; r++) {
        int s = wid + r * 16;
        const float* row = g_xg + s * C_DIM;
        float acc = 0.f;
        #pragma unroll
        for (int j = 0; j < C_DIM / 32; j++) {          // 12 elements per lane
            int c = lane + j * 32;
            acc = fmaf(row[c], w_lin[c], acc);
        }
        #pragma unroll
        for (int off = 16; off > 0; off >>= 1)
            acc += __shfl_down_sync(0xFFFFFFFFu, acc, off);
        if (lane == 0) sc[s] = acc;
    }
    __syncthreads();

    // --- stable rank: rank(i) = #{j : sc[j] > sc[i] or (== and j < i)} ---
    if (t < S_DIM) {
        float si = sc[t];
        int rank = 0;
        #pragma unroll 8
        for (int j = 0; j < S_DIM; j++) {
            float sj = sc[j];
            rank += (sj > si || (sj == si && j < t)) ? 1 : 0;
        }
        flag[t] = (rank < S_TOP) ? 1 : 0;
    }
    __syncthreads();
    if (t == 0) {                            // trivial 64-iter compaction
        int n = 0;
        for (int i = 0; i < S_DIM; i++)
            if (flag[i] && n < S_TOP) g_idx[n++] = i;
    }
}

// ---------------------------------------------------------------------------
// Kernel 2b: per-channel kernel-generating MLP + softmax. 3 blocks x 128
// threads (one thread per channel) -> runs on 3 SMs in parallel.
// ---------------------------------------------------------------------------
__global__ void mlp_chan_kernel(const float* __restrict__ w1,
                                const float* __restrict__ bn_gamma,
                                const float* __restrict__ bn_beta,
                                const float* __restrict__ bn_mean,
                                const float* __restrict__ bn_var,
                                const float* __restrict__ w2) {
    int c = blockIdx.x * blockDim.x + threadIdx.x;
    if (c >= C_DIM) return;

    __shared__ int idx[S_TOP];
    if (threadIdx.x < S_TOP) idx[threadIdx.x] = g_idx[threadIdx.x];
    __syncthreads();

    float sls[S_TOP];
    #pragma unroll
    for (int j = 0; j < S_TOP; j++) sls[j] = g_xg[idx[j] * C_DIM + c];

    float l0 = 0.f, l1 = 0.f, l2 = 0.f;
    #pragma unroll 4
    for (int k = 0; k < 2 * S_TOP; k++) {
        float acc = 0.f;
        const float* w1row = w1 + k * S_TOP;
        #pragma unroll
        for (int j = 0; j < S_TOP; j++) acc = fmaf(sls[j], w1row[j], acc);
        // BN (eval mode) + ReLU
        float scale = bn_gamma[k] * rsqrtf(bn_var[k] + 1e-5f);
        acc = fmaf(acc - bn_mean[k], scale, bn_beta[k]);
        acc = fmaxf(acc, 0.f);
        l0 = fmaf(acc, w2[0 * 2 * S_TOP + k], l0);
        l1 = fmaf(acc, w2[1 * 2 * S_TOP + k], l1);
        l2 = fmaf(acc, w2[2 * 2 * S_TOP + k], l2);
    }
    float mx = fmaxf(l0, fmaxf(l1, l2));
    float e0 = __expf(l0 - mx), e1 = __expf(l1 - mx), e2 = __expf(l2 - mx);
    float inv = 1.0f / (e0 + e1 + e2);
    g_convk[c * 3 + 0] = e0 * inv;
    g_convk[c * 3 + 1] = e1 * inv;
    g_convk[c * 3 + 2] = e2 * inv;
}

// ---------------------------------------------------------------------------
// Kernel 3: channel shift + depthwise temporal conv (k=3, zero pad).
// Batch-load SEG+2 float4s (max MLP), then FMA + STG burst. seg is the FAST
// block dim so halo frames are same-wave neighbors' main-line reads -> L2.
// Reads default policy; writes __stcs (written once, never re-read).
// ---------------------------------------------------------------------------
__global__ void __launch_bounds__(CONV_T)
conv_kernel(const float* __restrict__ x, float* __restrict__ out) {
    int b     = blockIdx.x;
    int seg   = b & (NSEG - 1);              // fast dim: waves mix all segments
    int chunk = b >> 3;                      // 0 .. BLK_PER_SEG-1
    int task  = chunk * CONV_T + threadIdx.x;   // < NQUADS (exact multiple)
    int c = task / HW4;
    int q = task - c * HW4;
    size_t base = (size_t)c * HW + (size_t)q * 4;   // float index, 16B aligned
    int t0 = seg * SEG;

    // channel shift: c<48 -> read x[s+1]; 48<=c<96 -> x[s-1]; else x[s]
    int d = (c < CNUM) ? 1 : ((c < 2 * CNUM) ? -1 : 0);

    float k0 = g_convk[c * 3 + 0];
    float k1 = g_convk[c * 3 + 1];
    float k2 = g_convk[c * 3 + 2];

    const float4 zero4 = make_float4(0.f, 0.f, 0.f, 0.f);

    // Phase 1: batch load t0-1 .. t0+SEG (SEG+2 independent LDG.128)
    float4 v[SEG + 2];
    #pragma unroll
    for (int i = 0; i < SEG + 2; i++) {
        int t  = t0 - 1 + i;
        int ts = t + d;
        v[i] = ((unsigned)t < (unsigned)S_DIM && (unsigned)ts < (unsigned)S_DIM)
             ? *reinterpret_cast<const float4*>(x + (size_t)ts * CHW + base)
             : zero4;
    }

    // Phase 2: FMA + store burst
    #pragma unroll
    for (int i = 0; i < SEG; i++) {
        float4 a = v[i], bb = v[i + 1], cc = v[i + 2];
        float4 o;
        o.x = fmaf(k0, a.x, fmaf(k1, bb.x, k2 * cc.x));
        o.y = fmaf(k0, a.y, fmaf(k1, bb.y, k2 * cc.y));
        o.z = fmaf(k0, a.z, fmaf(k1, bb.z, k2 * cc.z));
        o.w = fmaf(k0, a.w, fmaf(k1, bb.w, k2 * cc.w));
        __stcs(reinterpret_cast<float4*>(out + (size_t)(t0 + i) * CHW + base), o);
    }
}

// ---------------------------------------------------------------------------
extern "C" void kernel_launch(void* const* d_in, const int* in_sizes, int n_in,
                              void* d_out, int out_size) {
    const float* x        = (const float*)d_in[0];
    const float* w_lin    = (const float*)d_in[1];
    const float* w1       = (const float*)d_in[2];
    const float* bn_gamma = (const float*)d_in[3];
    const float* bn_beta  = (const float*)d_in[4];
    const float* bn_mean  = (const float*)d_in[5];
    const float* bn_var   = (const float*)d_in[6];
    const float* w2       = (const float*)d_in[7];
    float* out            = (float*)d_out;

    pool_kernel<<<S_DIM * C_DIM, 128>>>(x);
    mlp_topk_kernel<<<1, 512>>>(w_lin);
    mlp_chan_kernel<<<3, 128>>>(w1, bn_gamma, bn_beta, bn_mean, bn_var, w2);
    conv_kernel<<<NSEG * BLK_PER_SEG, CONV_T>>>(x, out);
}

// round 13
// speedup vs baseline: 1.2167x; 1.0977x over previous
#include <cuda_runtime.h>
#include <cuda_bf16.h>

// Shapes (fixed per reference)
#define S_DIM   64
#define C_DIM   384
#define HW      3136          // 56*56
#define HW4     784           // HW/4 (float4 quads per channel plane)
#define CHW     (C_DIM * HW)  // 1204224 floats per frame
#define S_TOP   16
#define CNUM    48            // C_DIM / 8

#define SEG     8             // frames per conv segment
#define NSEG    (S_DIM / SEG) // 8
#define NQUADS  (C_DIM * HW4) // 301056 (c, quad) tasks
#define CONV_T  256           // conv block size
#define BLK_PER_SEG (NQUADS / CONV_T)  // 1176, exact

// Scratch (no device allocation allowed)
__device__ float g_xg[S_DIM * C_DIM];     // per-frame, per-channel means
__device__ float g_convk[C_DIM * 3];      // per-channel temporal kernel (softmaxed)

__device__ __forceinline__ void griddep_launch() {
    asm volatile("griddepcontrol.launch_dependents;");
}
__device__ __forceinline__ void griddep_wait() {
    asm volatile("griddepcontrol.wait;" ::: "memory");
}

// ---------------------------------------------------------------------------
// Kernel 1: global average pool. One block per (s,c) plane of 3136 floats.
// Triggers dependent (mlp) launch at entry so mlp's weight prefetch overlaps.
// ---------------------------------------------------------------------------
__global__ void pool_kernel(const float* __restrict__ x) {
    griddep_launch();
    int plane = blockIdx.x;                 // = s*C_DIM + c (x is (s,c,h,w) contiguous)
    const float4* p = reinterpret_cast<const float4*>(x + (size_t)plane * HW);
    float sum = 0.f;
    for (int i = threadIdx.x; i < HW4; i += blockDim.x) {
        float4 v = __ldcs(p + i);           // streaming read: evict-first
        sum += (v.x + v.y) + (v.z + v.w);
    }
    // warp reduce
    #pragma unroll
    for (int off = 16; off > 0; off >>= 1)
        sum += __shfl_down_sync(0xFFFFFFFFu, sum, off);
    __shared__ float warp_sums[4];          // 128 threads = 4 warps
    int lane = threadIdx.x & 31, wid = threadIdx.x >> 5;
    if (lane == 0) warp_sums[wid] = sum;
    __syncthreads();
    if (threadIdx.x == 0) {
        float t = warp_sums[0] + warp_sums[1] + warp_sums[2] + warp_sums[3];
        g_xg[plane] = t * (1.0f / (float)HW);
    }
}

// ---------------------------------------------------------------------------
// Kernel 2 (fused): scores -> stable top-16 -> per-channel MLP -> softmax.
// Single block, 512 threads (16 warps). PDL: weights prefetched to smem
// BEFORE griddepcontrol.wait (overlaps pool tail); g_xg-dependent phases
// after. Triggers conv launch at entry so conv's x-load phase overlaps.
// ---------------------------------------------------------------------------
__global__ void mlp_kernel(const float* __restrict__ w_lin,
                           const float* __restrict__ w1,
                           const float* __restrict__ bn_gamma,
                           const float* __restrict__ bn_beta,
                           const float* __restrict__ bn_mean,
                           const float* __restrict__ bn_var,
                           const float* __restrict__ w2) {
    griddep_launch();

    __shared__ float s_wlin[C_DIM];
    __shared__ float s_w1[2 * S_TOP * S_TOP];   // 512
    __shared__ float s_w2[3 * 2 * S_TOP];       // 96
    __shared__ float s_scale[2 * S_TOP], s_mean[2 * S_TOP], s_beta[2 * S_TOP];
    __shared__ float sc[S_DIM];
    __shared__ int   flag[S_DIM];
    __shared__ int   idx[S_TOP];

    int t    = threadIdx.x;
    int lane = t & 31;
    int wid  = t >> 5;                      // 0..15

    // --- pre-wait: prefetch all weights into smem (independent of pool) ---
    if (t < C_DIM) s_wlin[t] = w_lin[t];
    if (t < 2 * S_TOP * S_TOP) s_w1[t] = w1[t];
    if (t < 3 * 2 * S_TOP) s_w2[t] = w2[t];
    if (t < 2 * S_TOP) {
        s_scale[t] = bn_gamma[t] * rsqrtf(bn_var[t] + 1e-5f);
        s_mean[t]  = bn_mean[t];
        s_beta[t]  = bn_beta[t];
    }
    __syncthreads();

    griddep_wait();                          // g_xg now visible

    // --- scores: xgs[s] = dot(xg[s,:], w_lin); one warp per frame ---
    #pragma unroll
    for (int r = 0; r < S_DIM / 16; r++) {
        int s = wid + r * 16;
        const float* row = g_xg + s * C_DIM;
        float acc = 0.f;
        #pragma unroll
        for (int j = 0; j < C_DIM / 32; j++) {          // 12 elements per lane
            int c = lane + j * 32;
            acc = fmaf(row[c], s_wlin[c], acc);
        }
        #pragma unroll
        for (int off = 16; off > 0; off >>= 1)
            acc += __shfl_down_sync(0xFFFFFFFFu, acc, off);
        if (lane == 0) sc[s] = acc;
    }
    __syncthreads();

    // --- stable rank: rank(i) = #{j : sc[j] > sc[i] or (== and j < i)} ---
    if (t < S_DIM) {
        float si = sc[t];
        int rank = 0;
        #pragma unroll 8
        for (int j = 0; j < S_DIM; j++) {
            float sj = sc[j];
            rank += (sj > si || (sj == si && j < t)) ? 1 : 0;
        }
        flag[t] = (rank < S_TOP) ? 1 : 0;
    }
    __syncthreads();
    if (t == 0) {                            // trivial 64-iter compaction
        int n = 0;
        for (int i = 0; i < S_DIM; i++)
            if (flag[i] && n < S_TOP) idx[n++] = i;
    }
    __syncthreads();

    // --- per-channel kernel-generating MLP (threads 0..383) ---
    if (t < C_DIM) {
        float sls[S_TOP];
        #pragma unroll
        for (int j = 0; j < S_TOP; j++) sls[j] = g_xg[idx[j] * C_DIM + t];

        float l0 = 0.f, l1 = 0.f, l2 = 0.f;
        #pragma unroll 4
        for (int k = 0; k < 2 * S_TOP; k++) {
            float acc = 0.f;
            const float* w1row = s_w1 + k * S_TOP;
            #pragma unroll
            for (int j = 0; j < S_TOP; j++) acc = fmaf(sls[j], w1row[j], acc);
            acc = fmaf(acc - s_mean[k], s_scale[k], s_beta[k]);   // BN (eval)
            acc = fmaxf(acc, 0.f);                                // ReLU
            l0 = fmaf(acc, s_w2[0 * 2 * S_TOP + k], l0);
            l1 = fmaf(acc, s_w2[1 * 2 * S_TOP + k], l1);
            l2 = fmaf(acc, s_w2[2 * 2 * S_TOP + k], l2);
        }
        float mx = fmaxf(l0, fmaxf(l1, l2));
        float e0 = __expf(l0 - mx), e1 = __expf(l1 - mx), e2 = __expf(l2 - mx);
        float inv = 1.0f / (e0 + e1 + e2);
        g_convk[t * 3 + 0] = e0 * inv;
        g_convk[t * 3 + 1] = e1 * inv;
        g_convk[t * 3 + 2] = e2 * inv;
    }
}

// ---------------------------------------------------------------------------
// Kernel 3: channel shift + depthwise temporal conv (k=3, zero pad).
// PDL: launches while mlp runs; issues ALL x loads (independent of convk)
// before griddepcontrol.wait, reads g_convk after. seg is the FAST block dim
// (same-wave halo -> L2). Writes __stcs (written once, never re-read).
// ---------------------------------------------------------------------------
__global__ void __launch_bounds__(CONV_T)
conv_kernel(const float* __restrict__ x, float* __restrict__ out) {
    int b     = blockIdx.x;
    int seg   = b & (NSEG - 1);              // fast dim: waves mix all segments
    int chunk = b >> 3;                      // 0 .. BLK_PER_SEG-1
    int task  = chunk * CONV_T + threadIdx.x;   // < NQUADS (exact multiple)
    int c = task / HW4;
    int q = task - c * HW4;
    size_t base = (size_t)c * HW + (size_t)q * 4;   // float index, 16B aligned
    int t0 = seg * SEG;

    // channel shift: c<48 -> read x[s+1]; 48<=c<96 -> x[s-1]; else x[s]
    int d = (c < CNUM) ? 1 : ((c < 2 * CNUM) ? -1 : 0);

    const float4 zero4 = make_float4(0.f, 0.f, 0.f, 0.f);

    // Phase 1 (pre-wait): batch load t0-1 .. t0+SEG (SEG+2 independent LDG.128)
    float4 v[SEG + 2];
    #pragma unroll
    for (int i = 0; i < SEG + 2; i++) {
        int t  = t0 - 1 + i;
        int ts = t + d;
        v[i] = ((unsigned)t < (unsigned)S_DIM && (unsigned)ts < (unsigned)S_DIM)
             ? *reinterpret_cast<const float4*>(x + (size_t)ts * CHW + base)
             : zero4;
    }

    griddep_wait();                          // g_convk now visible

    float k0 = g_convk[c * 3 + 0];
    float k1 = g_convk[c * 3 + 1];
    float k2 = g_convk[c * 3 + 2];

    // Phase 2: FMA + store burst
    #pragma unroll
    for (int i = 0; i < SEG; i++) {
        float4 a = v[i], bb = v[i + 1], cc = v[i + 2];
        float4 o;
        o.x = fmaf(k0, a.x, fmaf(k1, bb.x, k2 * cc.x));
        o.y = fmaf(k0, a.y, fmaf(k1, bb.y, k2 * cc.y));
        o.z = fmaf(k0, a.z, fmaf(k1, bb.z, k2 * cc.z));
        o.w = fmaf(k0, a.w, fmaf(k1, bb.w, k2 * cc.w));
        __stcs(reinterpret_cast<float4*>(out + (size_t)(t0 + i) * CHW + base), o);
    }
}

// ---------------------------------------------------------------------------
extern "C" void kernel_launch(void* const* d_in, const int* in_sizes, int n_in,
                              void* d_out, int out_size) {
    const float* x        = (const float*)d_in[0];
    const float* w_lin    = (const float*)d_in[1];
    const float* w1       = (const float*)d_in[2];
    const float* bn_gamma = (const float*)d_in[3];
    const float* bn_beta  = (const float*)d_in[4];
    const float* bn_mean  = (const float*)d_in[5];
    const float* bn_var   = (const float*)d_in[6];
    const float* w2       = (const float*)d_in[7];
    float* out            = (float*)d_out;

    pool_kernel<<<S_DIM * C_DIM, 128>>>(x);

    // mlp: PDL secondary of pool
    {
        cudaLaunchConfig_t cfg = {};
        cfg.gridDim  = dim3(1, 1, 1);
        cfg.blockDim = dim3(512, 1, 1);
        cudaLaunchAttribute attr[1];
        attr[0].id = cudaLaunchAttributeProgrammaticStreamSerialization;
        attr[0].val.programmaticStreamSerializationAllowed = 1;
        cfg.attrs = attr;
        cfg.numAttrs = 1;
        cudaLaunchKernelEx(&cfg, mlp_kernel,
                           w_lin, w1, bn_gamma, bn_beta, bn_mean, bn_var, w2);
    }

    // conv: PDL secondary of mlp — load phase overlaps mlp execution
    {
        cudaLaunchConfig_t cfg = {};
        cfg.gridDim  = dim3(NSEG * BLK_PER_SEG, 1, 1);
        cfg.blockDim = dim3(CONV_T, 1, 1);
        cudaLaunchAttribute attr[1];
        attr[0].id = cudaLaunchAttributeProgrammaticStreamSerialization;
        attr[0].val.programmaticStreamSerializationAllowed = 1;
        cfg.attrs = attr;
        cfg.numAttrs = 1;
        cudaLaunchKernelEx(&cfg, conv_kernel, x, out);
    }
}